// round 15
// baseline (speedup 1.0000x reference)
#include <cuda_runtime.h>
#include <cuda_bf16.h>
#include <cstdint>
#include <math.h>

#define MDIM 64
#define NDIM 4096
#define BN   64
#define NST  2
#define KSPL 1024
#define NCH  (KSPL / 64)     // 16 chunks per K-split
#define NSPLIT (NDIM / KSPL) // 4
#define KCHEB 14
#define SLAB (MDIM * NDIM)   // one partial slab (floats)

#define TILEP 16384                    // 64x64 bf16 hi+lo pair
#define STAGE_BYTES 32768              // A pair + B pair
#define TX_BYTES 32768
#define GEMM_SMEM (128 + NST * STAGE_BYTES)   // 65664 -> 3 blocks/SM

#define GST 72
#define TST 40

// Scratch (allocation-free rule: __device__ globals)
__device__ float g_Gt[MDIM * MDIM];
__device__ float g_Yp[NSPLIT * SLAB];   // Y partials per K-split
__device__ float g_Zp[NSPLIT * SLAB];   // Z partials per K-split
__device__ __align__(128) char g_Qt[(size_t)64 * 64 * TILEP];  // Q_S tiles [rb][cc]
__device__ __align__(128) char g_Xt[64 * TILEP];               // X tiles   [kc]
__device__ __align__(128) char g_Ztt[64 * TILEP];              // Z~ tiles  [kc]

// ---------------------------------------------------------------------------
// PTX helpers
// ---------------------------------------------------------------------------
__device__ __forceinline__ uint32_t sptr(const void* p) {
    return (uint32_t)__cvta_generic_to_shared(p);
}
__device__ __forceinline__ void ldsm4(uint32_t r[4], uint32_t addr) {
    asm volatile("ldmatrix.sync.aligned.m8n8.x4.shared.b16 {%0,%1,%2,%3}, [%4];"
                 : "=r"(r[0]), "=r"(r[1]), "=r"(r[2]), "=r"(r[3]) : "r"(addr));
}
__device__ __forceinline__ void ldsm4t(uint32_t r[4], uint32_t addr) {
    asm volatile("ldmatrix.sync.aligned.m8n8.x4.trans.shared.b16 {%0,%1,%2,%3}, [%4];"
                 : "=r"(r[0]), "=r"(r[1]), "=r"(r[2]), "=r"(r[3]) : "r"(addr));
}
__device__ __forceinline__ void mma16816(float d[4], const uint32_t a[4],
                                         uint32_t b0, uint32_t b1) {
    asm volatile("mma.sync.aligned.m16n8k16.row.col.f32.bf16.bf16.f32 "
                 "{%0,%1,%2,%3}, {%4,%5,%6,%7}, {%8,%9}, {%0,%1,%2,%3};"
                 : "+f"(d[0]), "+f"(d[1]), "+f"(d[2]), "+f"(d[3])
                 : "r"(a[0]), "r"(a[1]), "r"(a[2]), "r"(a[3]),
                   "r"(b0), "r"(b1));
}
__device__ __forceinline__ void bulk_ld(uint32_t dst, const void* src,
                                        uint32_t bytes, uint32_t mbar) {
    asm volatile("cp.async.bulk.shared::cluster.global.mbarrier::complete_tx::bytes "
                 "[%0], [%1], %2, [%3];"
                 :: "r"(dst), "l"(src), "r"(bytes), "r"(mbar) : "memory");
}
__device__ __forceinline__ void mbar_init(uint32_t a, uint32_t cnt) {
    asm volatile("mbarrier.init.shared.b64 [%0], %1;" :: "r"(a), "r"(cnt) : "memory");
}
__device__ __forceinline__ void mbar_expect_tx(uint32_t a, uint32_t bytes) {
    asm volatile("mbarrier.arrive.expect_tx.shared.b64 _, [%0], %1;"
                 :: "r"(a), "r"(bytes) : "memory");
}
__device__ __forceinline__ void mbar_wait(uint32_t a, uint32_t parity) {
    asm volatile(
        "{\n\t.reg .pred P;\n\t"
        "WAIT_%=:\n\t"
        "mbarrier.try_wait.parity.acquire.cta.shared::cta.b64 P, [%0], %1, 0x989680;\n\t"
        "@P bra.uni DONE_%=;\n\t"
        "bra.uni WAIT_%=;\n\t"
        "DONE_%=:\n\t}"
        :: "r"(a), "r"(parity) : "memory");
}
__device__ __forceinline__ void fence_async_init() {
    asm volatile("fence.proxy.async.shared::cta;" ::: "memory");
}

__device__ __forceinline__ void bf16split(float x, __nv_bfloat16& h, __nv_bfloat16& l) {
    h = __float2bfloat16(x);
    l = __float2bfloat16(x - __bfloat162float(h));
}
__device__ __forceinline__ void split2pack(float a, float b, uint32_t& hp, uint32_t& lp) {
    __nv_bfloat16 ha, la, hb, lb;
    bf16split(a, ha, la);
    bf16split(b, hb, lb);
    __nv_bfloat162 h; h.x = ha; h.y = hb;
    __nv_bfloat162 l; l.x = la; l.y = lb;
    hp = *(uint32_t*)&h;
    lp = *(uint32_t*)&l;
}

// ---------------------------------------------------------------------------
// Convert Q_S and X into tiled, pre-swizzled bf16 hi/lo tile pairs
// ---------------------------------------------------------------------------
__global__ __launch_bounds__(256) void conv_kernel(const float4* __restrict__ Q,
                                                   const float4* __restrict__ X) {
    const size_t QN4 = (size_t)NDIM * NDIM / 4;
    size_t gid = (size_t)blockIdx.x * 256 + threadIdx.x;
    float4 v;
    char* base;
    uint32_t r, c;
    if (gid < QN4) {
        v = Q[gid];
        r = (uint32_t)(gid >> 10);
        c = ((uint32_t)gid & 1023) * 4;
        base = g_Qt + ((size_t)((r >> 6) * 64 + (c >> 6))) * TILEP;
    } else {
        size_t x = gid - QN4;
        v = X[x];
        r = (uint32_t)(x >> 10);
        c = ((uint32_t)x & 1023) * 4;
        base = g_Xt + (size_t)(c >> 6) * TILEP;
    }
    const uint32_t i = r & 63, j = c & 63;
    const uint32_t sw = (i * 128 + j * 2) ^ ((i & 7) << 4);
    uint32_t h0, l0, h1, l1;
    split2pack(v.x, v.y, h0, l0);
    split2pack(v.z, v.w, h1, l1);
    *(uint2*)(base + sw)        = make_uint2(h0, h1);
    *(uint2*)(base + 8192 + sw) = make_uint2(l0, l1);
}

// ---------------------------------------------------------------------------
// Z = sum of 4 partial slabs (deterministic fixed-order reduce)
// ---------------------------------------------------------------------------
__global__ __launch_bounds__(256) void reduce_z(float4* __restrict__ Z) {
    const int i = blockIdx.x * 256 + threadIdx.x;   // 65536 float4 total
    const float4* P = (const float4*)g_Zp;
    const int SL4 = SLAB / 4;
    float4 a = P[i], b = P[SL4 + i], c = P[2 * SL4 + i], d = P[3 * SL4 + i];
    Z[i] = make_float4(a.x + b.x + c.x + d.x, a.y + b.y + c.y + d.y,
                       a.z + b.z + c.z + d.z, a.w + b.w + c.w + d.w);
}

// ---------------------------------------------------------------------------
// G~ = 2 * (F^T F) / (||F^T F||_F + 1e-12) - I
// ---------------------------------------------------------------------------
__global__ __launch_bounds__(256) void prep_kernel(const float* __restrict__ F) {
    __shared__ float Fs[MDIM][MDIM + 1];
    __shared__ float FFs[MDIM][MDIM + 4];
    __shared__ float red[8];
    __shared__ float s_inv;

    int t = threadIdx.x;
    for (int o = t; o < MDIM * MDIM; o += 256)
        Fs[o >> 6][o & 63] = F[o];
    __syncthreads();

    int i  = t >> 2;
    int j0 = (t & 3) * 16;
    float acc[16];
#pragma unroll
    for (int u = 0; u < 16; u++) acc[u] = 0.0f;
    for (int k = 0; k < MDIM; k++) {
        float a = Fs[k][i];
#pragma unroll
        for (int u = 0; u < 16; u++) acc[u] = fmaf(a, Fs[k][j0 + u], acc[u]);
    }
    float ss = 0.0f;
#pragma unroll
    for (int u = 0; u < 16; u++) {
        FFs[i][j0 + u] = acc[u];
        ss = fmaf(acc[u], acc[u], ss);
    }
#pragma unroll
    for (int off = 16; off > 0; off >>= 1)
        ss += __shfl_xor_sync(0xffffffffu, ss, off);
    if ((t & 31) == 0) red[t >> 5] = ss;
    __syncthreads();
    if (t == 0) {
        float tot = 0.0f;
        for (int w = 0; w < 8; w++) tot += red[w];
        s_inv = 2.0f / (sqrtf(tot) + 1e-12f);
    }
    __syncthreads();
    float inv = s_inv;
#pragma unroll
    for (int u = 0; u < 16; u++) {
        int j = j0 + u;
        g_Gt[i * MDIM + j] = FFs[i][j] * inv - (i == j ? 1.0f : 0.0f);
    }
}

// ---------------------------------------------------------------------------
// TMA-staged bf16 tensor GEMM on pre-swizzled tiles (R12 core).
// NST=2 double-buffer (3 blocks/SM), 2 TMA bulks/chunk by thread 0,
// one __syncthreads per chunk, plain-store partial-slab epilogue.
// TRANSB=0: B tile = Qt[kc][jb];  TRANSB=1: B tile = Qt[jb][kc].
// ---------------------------------------------------------------------------
template <int TRANSB>
__global__ __launch_bounds__(256) void gemm_bf(const char* __restrict__ At,
                                               const char* __restrict__ Bt,
                                               float* __restrict__ Cp) {
    extern __shared__ __align__(128) char sm[];
    const uint32_t smb = sptr(sm);

    const int t    = threadIdx.x;
    const int lane = t & 31;
    const int warp = t >> 5;
    const int jb   = blockIdx.x;
    const int jg   = jb * BN;
    const int kb0  = blockIdx.y * (KSPL / 64);
    const int mw   = (warp & 3) * 16;
    const int nw   = (warp >> 2) * 32;
    const int lr   = lane & 15;
    const int g8   = (lane >> 4) * 8;

    if (t == 0) {
#pragma unroll
        for (int s = 0; s < NST; s++)
            mbar_init(smb + s * 16, 1);     // full barriers only
        fence_async_init();
    }
    __syncthreads();

    const char* srcA = At + (size_t)kb0 * TILEP;
    const char* srcB = Bt + (TRANSB ? ((size_t)jb * 64 + kb0)
                                    : ((size_t)kb0 * 64 + jb)) * TILEP;
    const long dB = TRANSB ? TILEP : (long)64 * TILEP;
    const uint32_t stage0 = smb + 128;

    // per-thread swizzled ldsm offsets (loop-invariant)
    const uint32_t xorv = (uint32_t)(lane & 7) << 4;
    uint32_t aoffs[4];
#pragma unroll
    for (int ks = 0; ks < 4; ks++)
        aoffs[ks] = (uint32_t)(mw + lr) * 128 + (((uint32_t)(ks * 32 + g8 * 2)) ^ xorv);
    uint32_t boffs[4][2];
#pragma unroll
    for (int ks = 0; ks < 4; ks++)
#pragma unroll
        for (int half = 0; half < 2; half++) {
            if (TRANSB == 0)
                boffs[ks][half] = (uint32_t)(ks * 16 + lr) * 128 +
                                  (((uint32_t)((nw + half * 16 + g8) * 2)) ^ xorv);
            else
                boffs[ks][half] = (uint32_t)(nw + half * 16 + lr) * 128 +
                                  (((uint32_t)(ks * 32 + g8 * 2)) ^ xorv);
        }

    float acc[4][4];
#pragma unroll
    for (int nt = 0; nt < 4; nt++)
#pragma unroll
        for (int u = 0; u < 4; u++) acc[nt][u] = 0.0f;

    // prologue: issue chunks 0,1 into stages 0,1
    if (t == 0) {
#pragma unroll
        for (int cn = 0; cn < NST; cn++) {
            const uint32_t full = smb + cn * 16;
            mbar_expect_tx(full, TX_BYTES);
            bulk_ld(stage0 + cn * STAGE_BYTES,         srcA + (long)cn * TILEP, TILEP, full);
            bulk_ld(stage0 + cn * STAGE_BYTES + TILEP, srcB + (long)cn * dB,    TILEP, full);
        }
    }

#pragma unroll
    for (int c = 0; c < NCH; c++) {
        const int s = c & 1;
        mbar_wait(smb + s * 16, (c >> 1) & 1);

        const uint32_t Ah = stage0 + s * STAGE_BYTES;
        const uint32_t Al = Ah + 8192;
        const uint32_t Bh = Ah + TILEP;
        const uint32_t Bl = Bh + 8192;

#pragma unroll
        for (int ks = 0; ks < 4; ks++) {
            uint32_t ah[4], al[4];
            ldsm4(ah, Ah + aoffs[ks]);
            ldsm4(al, Al + aoffs[ks]);
#pragma unroll
            for (int half = 0; half < 2; half++) {
                uint32_t bh[4], bl[4];
                if (TRANSB == 0) {
                    ldsm4t(bh, Bh + boffs[ks][half]);
                    ldsm4t(bl, Bl + boffs[ks][half]);
                    mma16816(acc[half * 2],     ah, bh[0], bh[1]);
                    mma16816(acc[half * 2],     ah, bl[0], bl[1]);
                    mma16816(acc[half * 2],     al, bh[0], bh[1]);
                    mma16816(acc[half * 2 + 1], ah, bh[2], bh[3]);
                    mma16816(acc[half * 2 + 1], ah, bl[2], bl[3]);
                    mma16816(acc[half * 2 + 1], al, bh[2], bh[3]);
                } else {
                    ldsm4(bh, Bh + boffs[ks][half]);
                    ldsm4(bl, Bl + boffs[ks][half]);
                    mma16816(acc[half * 2],     ah, bh[0], bh[2]);
                    mma16816(acc[half * 2],     ah, bl[0], bl[2]);
                    mma16816(acc[half * 2],     al, bh[0], bh[2]);
                    mma16816(acc[half * 2 + 1], ah, bh[1], bh[3]);
                    mma16816(acc[half * 2 + 1], ah, bl[1], bl[3]);
                    mma16816(acc[half * 2 + 1], al, bh[1], bh[3]);
                }
            }
        }

        __syncthreads();          // all warps done reading stage s
        const int cn = c + NST;
        if (cn < NCH && t == 0) {
            const uint32_t full = smb + s * 16;
            mbar_expect_tx(full, TX_BYTES);
            bulk_ld(stage0 + s * STAGE_BYTES,         srcA + (long)cn * TILEP, TILEP, full);
            bulk_ld(stage0 + s * STAGE_BYTES + TILEP, srcB + (long)cn * dB,    TILEP, full);
        }
    }

    // epilogue: plain stores into this K-split's partial slab
    float* Cs = Cp + (size_t)blockIdx.y * SLAB;
    const int row = mw + (lane >> 2);
#pragma unroll
    for (int nt = 0; nt < 4; nt++) {
        const int col = jg + nw + (nt >> 1) * 16 + (nt & 1) * 8 + (lane & 3) * 2;
        *(float2*)&Cs[(size_t)row * NDIM + col]       = make_float2(acc[nt][0], acc[nt][1]);
        *(float2*)&Cs[(size_t)(row + 8) * NDIM + col] = make_float2(acc[nt][2], acc[nt][3]);
    }
}

// ---------------------------------------------------------------------------
// Tensor-core Chebyshev. Sums the 4 Y partial slabs at load; recurrence init
// from the smem hi/lo pair. Output into tiled/pre-swizzled g_Ztt.
// ---------------------------------------------------------------------------
__global__ __launch_bounds__(256) void cheb_tc(const float* __restrict__ lamS,
                                               const float* __restrict__ gammap) {
    extern __shared__ __align__(16) __nv_bfloat16 cs[];
    __nv_bfloat16* Gh = cs;
    __nv_bfloat16* Gl = cs + 64 * GST;
    __nv_bfloat16* Tbh = cs + 2 * 64 * GST;
    __nv_bfloat16* Tbl = Tbh + 3 * 64 * TST;
    __shared__ float sh_base[32];
    __shared__ float sh_r[32];

    const int t    = threadIdx.x;
    const int lane = t & 31;
    const int warp = t >> 5;
    const int jg   = blockIdx.x * 32;
    const int mw   = (warp & 3) * 16;
    const int nw   = (warp >> 2) * 16;
    const int lr   = lane & 15;
    const int g8   = (lane >> 4) * 8;

    for (int o = t; o < MDIM * MDIM; o += 256) {
        int r = o >> 6, c = o & 63;
        __nv_bfloat16 h, l;
        bf16split(g_Gt[o], h, l);
        Gh[r * GST + c] = h;
        Gl[r * GST + c] = l;
    }
    for (int o = t; o < MDIM * 32; o += 256) {
        int r = o >> 5, c = o & 31;
        size_t idx = (size_t)r * NDIM + jg + c;
        float y = g_Yp[idx] + g_Yp[SLAB + idx] + g_Yp[2 * SLAB + idx] + g_Yp[3 * SLAB + idx];
        __nv_bfloat16 h, l;
        bf16split(y, h, l);
        Tbh[r * TST + c] = h;
        Tbl[r * TST + c] = l;
    }
    if (t < 32) {
        float gam = gammap[0];
        float a = gam * lamS[jg + t];
        float base, r;
        if (fabsf(a) < 1e-7f) {
            base = 1.0f; r = 0.0f;
        } else {
            float b  = 2.0f / a - 1.0f;
            float ab = fabsf(b);
            float s  = sqrtf(fmaf(ab, ab, -1.0f));
            float q  = 1.0f / (ab + s);
            float sg = (a > 0.0f) ? 1.0f : -1.0f;
            r    = sg * q;
            base = (2.0f / a) * sg * 2.0f * q / (1.0f - q * q);
        }
        sh_base[t] = base;
        sh_r[t]    = r;
    }
    __syncthreads();

    uint32_t gh[4][4], gl[4][4];
#pragma unroll
    for (int ks = 0; ks < 4; ks++) {
        ldsm4(gh[ks], sptr(Gh + (mw + lr) * GST + ks * 16 + g8));
        ldsm4(gl[ks], sptr(Gl + (mw + lr) * GST + ks * 16 + g8));
    }

    const int row0 = mw + (lane >> 2);
    float basev[2][2], rv[2][2], pv[2][2];
#pragma unroll
    for (int nt = 0; nt < 2; nt++) {
        int c0 = nw + nt * 8 + 2 * (lane & 3);
        basev[nt][0] = sh_base[c0];     basev[nt][1] = sh_base[c0 + 1];
        rv[nt][0]    = sh_r[c0];        rv[nt][1]    = sh_r[c0 + 1];
        pv[nt][0] = 2.0f * basev[nt][0] * rv[nt][0];
        pv[nt][1] = 2.0f * basev[nt][1] * rv[nt][1];
    }

    float acc[2][4], prev[2][4], tp[2][4];
#pragma unroll
    for (int nt = 0; nt < 2; nt++) {
        int c0 = nw + nt * 8 + 2 * (lane & 3);
        float y00 = (float)Tbh[row0 * TST + c0]           + (float)Tbl[row0 * TST + c0];
        float y01 = (float)Tbh[row0 * TST + c0 + 1]       + (float)Tbl[row0 * TST + c0 + 1];
        float y10 = (float)Tbh[(row0 + 8) * TST + c0]     + (float)Tbl[(row0 + 8) * TST + c0];
        float y11 = (float)Tbh[(row0 + 8) * TST + c0 + 1] + (float)Tbl[(row0 + 8) * TST + c0 + 1];
        prev[nt][0] = y00; prev[nt][1] = y01; prev[nt][2] = y10; prev[nt][3] = y11;
        acc[nt][0] = basev[nt][0] * y00;
        acc[nt][1] = basev[nt][1] * y01;
        acc[nt][2] = basev[nt][0] * y10;
        acc[nt][3] = basev[nt][1] * y11;
        tp[nt][0] = tp[nt][1] = tp[nt][2] = tp[nt][3] = 0.0f;
    }

    for (int k = 1; k < KCHEB; k++) {
        __syncthreads();
        const __nv_bfloat16* Th = Tbh + ((k - 1) % 3) * (64 * TST);
        const __nv_bfloat16* Tl = Tbl + ((k - 1) % 3) * (64 * TST);
        float u[2][4];
#pragma unroll
        for (int nt = 0; nt < 2; nt++)
#pragma unroll
            for (int i = 0; i < 4; i++) u[nt][i] = 0.0f;
#pragma unroll
        for (int ks = 0; ks < 4; ks++) {
            uint32_t th[4], tl[4];
            ldsm4t(th, sptr(Th + (ks * 16 + lr) * TST + nw + g8));
            ldsm4t(tl, sptr(Tl + (ks * 16 + lr) * TST + nw + g8));
            mma16816(u[0], gh[ks], th[0], th[1]);
            mma16816(u[0], gh[ks], tl[0], tl[1]);
            mma16816(u[0], gl[ks], th[0], th[1]);
            mma16816(u[1], gh[ks], th[2], th[3]);
            mma16816(u[1], gh[ks], tl[2], tl[3]);
            mma16816(u[1], gl[ks], th[2], th[3]);
        }
        float tn[2][4];
#pragma unroll
        for (int nt = 0; nt < 2; nt++)
#pragma unroll
            for (int i = 0; i < 4; i++)
                tn[nt][i] = (k == 1) ? u[nt][i] : fmaf(2.0f, u[nt][i], -tp[nt][i]);
#pragma unroll
        for (int nt = 0; nt < 2; nt++) {
            acc[nt][0] = fmaf(pv[nt][0], tn[nt][0], acc[nt][0]);
            acc[nt][1] = fmaf(pv[nt][1], tn[nt][1], acc[nt][1]);
            acc[nt][2] = fmaf(pv[nt][0], tn[nt][2], acc[nt][2]);
            acc[nt][3] = fmaf(pv[nt][1], tn[nt][3], acc[nt][3]);
            pv[nt][0] *= rv[nt][0];
            pv[nt][1] *= rv[nt][1];
        }
        if (k < KCHEB - 1) {
            __nv_bfloat16* Wh = Tbh + (k % 3) * (64 * TST);
            __nv_bfloat16* Wl = Tbl + (k % 3) * (64 * TST);
#pragma unroll
            for (int nt = 0; nt < 2; nt++) {
                int c0 = nw + nt * 8 + 2 * (lane & 3);
                uint32_t hp, lp;
                split2pack(tn[nt][0], tn[nt][1], hp, lp);
                *(uint32_t*)(Wh + row0 * TST + c0) = hp;
                *(uint32_t*)(Wl + row0 * TST + c0) = lp;
                split2pack(tn[nt][2], tn[nt][3], hp, lp);
                *(uint32_t*)(Wh + (row0 + 8) * TST + c0) = hp;
                *(uint32_t*)(Wl + (row0 + 8) * TST + c0) = lp;
            }
        }
#pragma unroll
        for (int nt = 0; nt < 2; nt++)
#pragma unroll
            for (int i = 0; i < 4; i++) {
                tp[nt][i]   = prev[nt][i];
                prev[nt][i] = tn[nt][i];
            }
    }

    {
        char* Zt = g_Ztt + (size_t)(jg >> 6) * TILEP;
        const uint32_t jo = jg & 63;
#pragma unroll
        for (int nt = 0; nt < 2; nt++) {
            const uint32_t c0 = nw + nt * 8 + 2 * (lane & 3);
            uint32_t hp, lp;
            split2pack(acc[nt][0], acc[nt][1], hp, lp);
            uint32_t o0 = (uint32_t)row0 * 128 + (((jo + c0) * 2) ^ (((uint32_t)row0 & 7) << 4));
            *(uint32_t*)(Zt + o0)        = hp;
            *(uint32_t*)(Zt + 8192 + o0) = lp;
            split2pack(acc[nt][2], acc[nt][3], hp, lp);
            uint32_t o1 = (uint32_t)(row0 + 8) * 128 + (((jo + c0) * 2) ^ (((uint32_t)row0 & 7) << 4));
            *(uint32_t*)(Zt + o1)        = hp;
            *(uint32_t*)(Zt + 8192 + o1) = lp;
        }
    }
}

#define CHEB_SMEM ((2 * 64 * GST + 6 * 64 * TST) * 2)

// ---------------------------------------------------------------------------
extern "C" void kernel_launch(void* const* d_in, const int* in_sizes, int n_in,
                              void* d_out, int out_size) {
    const float* X    = (const float*)d_in[0];   // (64, 4096)
    const float* F    = (const float*)d_in[1];   // (64, 64)
    const float* Q_S  = (const float*)d_in[2];   // (4096, 4096)
    const float* lamS = (const float*)d_in[3];   // (4096,)
    const float* gam  = (const float*)d_in[4];   // scalar
    float* Z = (float*)d_out;                    // (64, 4096)

    float *Yp, *Zp;
    char *Qt, *Xt, *Ztt;
    cudaGetSymbolAddress((void**)&Yp,  g_Yp);
    cudaGetSymbolAddress((void**)&Zp,  g_Zp);
    cudaGetSymbolAddress((void**)&Qt,  g_Qt);
    cudaGetSymbolAddress((void**)&Xt,  g_Xt);
    cudaGetSymbolAddress((void**)&Ztt, g_Ztt);

    static bool attr_set = false;
    if (!attr_set) {
        cudaFuncSetAttribute(gemm_bf<0>, cudaFuncAttributeMaxDynamicSharedMemorySize, GEMM_SMEM);
        cudaFuncSetAttribute(gemm_bf<1>, cudaFuncAttributeMaxDynamicSharedMemorySize, GEMM_SMEM);
        cudaFuncSetAttribute(cheb_tc,    cudaFuncAttributeMaxDynamicSharedMemorySize, CHEB_SMEM);
        attr_set = true;
    }

    const int conv_blocks = (NDIM * NDIM / 4 + MDIM * NDIM / 4) / 256;  // 16640
    dim3 ggrid(NDIM / BN, NSPLIT);

    conv_kernel<<<conv_blocks, 256>>>((const float4*)Q_S, (const float4*)X);
    prep_kernel<<<1, 256>>>(F);
    gemm_bf<0><<<ggrid, 256, GEMM_SMEM>>>(Xt, Qt, Yp);    // Yp[s] = partial X @ Q_S
    cheb_tc<<<NDIM / 32, 256, CHEB_SMEM>>>(lamS, gam);    // Ztt = f(G) (sum Yp)
    gemm_bf<1><<<ggrid, 256, GEMM_SMEM>>>(Ztt, Qt, Zp);   // Zp[s] = partial Z~ @ Q_S^T
    reduce_z<<<(MDIM * NDIM / 4) / 256, 256>>>((float4*)Z);
}

// round 16
// speedup vs baseline: 1.0676x; 1.0676x over previous
#include <cuda_runtime.h>
#include <cuda_bf16.h>
#include <cstdint>
#include <math.h>

#define MDIM 64
#define NDIM 4096
#define BN   64
#define NST  3
#define KSPL 1024
#define NCH  (KSPL / 64)     // 16 chunks per K-split
#define NSPLIT (NDIM / KSPL) // 4
#define KCHEB 12
#define BNC  16              // cheb columns per block

#define TILEP 16384                    // one 64x64 hi+lo tile pair (8192 + 8192)
#define STAGE_BYTES 32768              // A pair + B pair
#define TX_BYTES 32768
#define GEMM_SMEM (128 + NST * STAGE_BYTES)   // 98432

#define GST 72
#define TST 40

// Scratch (allocation-free rule: __device__ globals)
__device__ float g_Gt[MDIM * MDIM];
__device__ float g_Y [MDIM * NDIM];
// tiled, pre-swizzled bf16 hi/lo tile pairs (16KB each)
__device__ __align__(128) char g_Qt[(size_t)64 * 64 * TILEP];  // Q_S: [rb][cc]
__device__ __align__(128) char g_Xt[64 * TILEP];               // X:   [kc]
__device__ __align__(128) char g_Ztt[64 * TILEP];              // Z~:  [kc]

// ---------------------------------------------------------------------------
// PTX helpers
// ---------------------------------------------------------------------------
__device__ __forceinline__ uint32_t sptr(const void* p) {
    return (uint32_t)__cvta_generic_to_shared(p);
}
__device__ __forceinline__ void ldsm4(uint32_t r[4], uint32_t addr) {
    asm volatile("ldmatrix.sync.aligned.m8n8.x4.shared.b16 {%0,%1,%2,%3}, [%4];"
                 : "=r"(r[0]), "=r"(r[1]), "=r"(r[2]), "=r"(r[3]) : "r"(addr));
}
__device__ __forceinline__ void ldsm4t(uint32_t r[4], uint32_t addr) {
    asm volatile("ldmatrix.sync.aligned.m8n8.x4.trans.shared.b16 {%0,%1,%2,%3}, [%4];"
                 : "=r"(r[0]), "=r"(r[1]), "=r"(r[2]), "=r"(r[3]) : "r"(addr));
}
__device__ __forceinline__ void mma16816(float d[4], const uint32_t a[4],
                                         uint32_t b0, uint32_t b1) {
    asm volatile("mma.sync.aligned.m16n8k16.row.col.f32.bf16.bf16.f32 "
                 "{%0,%1,%2,%3}, {%4,%5,%6,%7}, {%8,%9}, {%0,%1,%2,%3};"
                 : "+f"(d[0]), "+f"(d[1]), "+f"(d[2]), "+f"(d[3])
                 : "r"(a[0]), "r"(a[1]), "r"(a[2]), "r"(a[3]),
                   "r"(b0), "r"(b1));
}
__device__ __forceinline__ void bulk_ld(uint32_t dst, const void* src,
                                        uint32_t bytes, uint32_t mbar) {
    asm volatile("cp.async.bulk.shared::cluster.global.mbarrier::complete_tx::bytes "
                 "[%0], [%1], %2, [%3];"
                 :: "r"(dst), "l"(src), "r"(bytes), "r"(mbar) : "memory");
}
__device__ __forceinline__ void mbar_init(uint32_t a, uint32_t cnt) {
    asm volatile("mbarrier.init.shared.b64 [%0], %1;" :: "r"(a), "r"(cnt) : "memory");
}
__device__ __forceinline__ void mbar_expect_tx(uint32_t a, uint32_t bytes) {
    asm volatile("mbarrier.arrive.expect_tx.shared.b64 _, [%0], %1;"
                 :: "r"(a), "r"(bytes) : "memory");
}
__device__ __forceinline__ void mbar_arrive(uint32_t a) {
    asm volatile("mbarrier.arrive.shared.b64 _, [%0];" :: "r"(a) : "memory");
}
__device__ __forceinline__ void mbar_wait(uint32_t a, uint32_t parity) {
    asm volatile(
        "{\n\t.reg .pred P;\n\t"
        "WAIT_%=:\n\t"
        "mbarrier.try_wait.parity.acquire.cta.shared::cta.b64 P, [%0], %1, 0x989680;\n\t"
        "@P bra.uni DONE_%=;\n\t"
        "bra.uni WAIT_%=;\n\t"
        "DONE_%=:\n\t}"
        :: "r"(a), "r"(parity) : "memory");
}
__device__ __forceinline__ void fence_async_init() {
    asm volatile("fence.proxy.async.shared::cta;" ::: "memory");
}

__device__ __forceinline__ void bf16split(float x, __nv_bfloat16& h, __nv_bfloat16& l) {
    h = __float2bfloat16(x);
    l = __float2bfloat16(x - __bfloat162float(h));
}
__device__ __forceinline__ void split2pack(float a, float b, uint32_t& hp, uint32_t& lp) {
    __nv_bfloat16 ha, la, hb, lb;
    bf16split(a, ha, la);
    bf16split(b, hb, lb);
    __nv_bfloat162 h; h.x = ha; h.y = hb;
    __nv_bfloat162 l; l.x = la; l.y = lb;
    hp = *(uint32_t*)&h;
    lp = *(uint32_t*)&l;
}

// ---------------------------------------------------------------------------
// Convert Q_S and X into tiled, pre-swizzled bf16 hi/lo tile pairs.
// ---------------------------------------------------------------------------
__global__ __launch_bounds__(256) void conv_kernel(const float4* __restrict__ Q,
                                                   const float4* __restrict__ X) {
    const size_t QN4 = (size_t)NDIM * NDIM / 4;
    size_t gid = (size_t)blockIdx.x * 256 + threadIdx.x;
    float4 v;
    char* base;
    uint32_t r, c;
    if (gid < QN4) {
        v = Q[gid];
        r = (uint32_t)(gid >> 10);
        c = ((uint32_t)gid & 1023) * 4;
        base = g_Qt + ((size_t)((r >> 6) * 64 + (c >> 6))) * TILEP;
    } else {
        size_t x = gid - QN4;
        v = X[x];
        r = (uint32_t)(x >> 10);
        c = ((uint32_t)x & 1023) * 4;
        base = g_Xt + (size_t)(c >> 6) * TILEP;
    }
    const uint32_t i = r & 63, j = c & 63;
    const uint32_t sw = (i * 128 + j * 2) ^ ((i & 7) << 4);
    uint32_t h0, l0, h1, l1;
    split2pack(v.x, v.y, h0, l0);
    split2pack(v.z, v.w, h1, l1);
    *(uint2*)(base + sw)        = make_uint2(h0, h1);
    *(uint2*)(base + 8192 + sw) = make_uint2(l0, l1);
}

// ---------------------------------------------------------------------------
// Zero-init Y and Z (outputs accumulated via atomicAdd each replay)
// ---------------------------------------------------------------------------
__global__ __launch_bounds__(256) void zero_kernel(float* __restrict__ a,
                                                   float* __restrict__ b) {
    int i = blockIdx.x * 256 + threadIdx.x;
    a[i] = 0.0f;
    b[i] = 0.0f;
}

// ---------------------------------------------------------------------------
// G~ = 2 * (F^T F) / (||F^T F||_F + 1e-12) - I
// ---------------------------------------------------------------------------
__global__ __launch_bounds__(256) void prep_kernel(const float* __restrict__ F) {
    __shared__ float Fs[MDIM][MDIM + 1];
    __shared__ float FFs[MDIM][MDIM + 4];
    __shared__ float red[8];
    __shared__ float s_inv;

    int t = threadIdx.x;
    for (int o = t; o < MDIM * MDIM; o += 256)
        Fs[o >> 6][o & 63] = F[o];
    __syncthreads();

    int i  = t >> 2;
    int j0 = (t & 3) * 16;
    float acc[16];
#pragma unroll
    for (int u = 0; u < 16; u++) acc[u] = 0.0f;
    for (int k = 0; k < MDIM; k++) {
        float a = Fs[k][i];
#pragma unroll
        for (int u = 0; u < 16; u++) acc[u] = fmaf(a, Fs[k][j0 + u], acc[u]);
    }
    float ss = 0.0f;
#pragma unroll
    for (int u = 0; u < 16; u++) {
        FFs[i][j0 + u] = acc[u];
        ss = fmaf(acc[u], acc[u], ss);
    }
#pragma unroll
    for (int off = 16; off > 0; off >>= 1)
        ss += __shfl_xor_sync(0xffffffffu, ss, off);
    if ((t & 31) == 0) red[t >> 5] = ss;
    __syncthreads();
    if (t == 0) {
        float tot = 0.0f;
        for (int w = 0; w < 8; w++) tot += red[w];
        s_inv = 2.0f / (sqrtf(tot) + 1e-12f);
    }
    __syncthreads();
    float inv = s_inv;
#pragma unroll
    for (int u = 0; u < 16; u++) {
        int j = j0 + u;
        g_Gt[i * MDIM + j] = FFs[i][j] * inv - (i == j ? 1.0f : 0.0f);
    }
}

// ---------------------------------------------------------------------------
// TMA-staged bf16 tensor GEMM on pre-swizzled tiles (R12 core, verbatim).
// NST=3 ring, 2 TMA bulks/chunk by thread 0, empty barriers (count 8).
// TRANSB=0: B tile = Qt[kc][jb];  TRANSB=1: B tile = Qt[jb][kc].
// ---------------------------------------------------------------------------
template <int TRANSB>
__global__ __launch_bounds__(256) void gemm_bf(const char* __restrict__ At,
                                               const char* __restrict__ Bt,
                                               float* __restrict__ C) {
    extern __shared__ __align__(128) char sm[];
    const uint32_t smb = sptr(sm);

    const int t    = threadIdx.x;
    const int lane = t & 31;
    const int warp = t >> 5;
    const int jb   = blockIdx.x;
    const int jg   = jb * BN;
    const int kb0  = blockIdx.y * (KSPL / 64);
    const int mw   = (warp & 3) * 16;
    const int nw   = (warp >> 2) * 32;
    const int lr   = lane & 15;
    const int g8   = (lane >> 4) * 8;

    if (t == 0) {
#pragma unroll
        for (int s = 0; s < NST; s++) {
            mbar_init(smb + s * 16, 1);     // full
            mbar_init(smb + s * 16 + 8, 8); // empty (one arrive per warp)
        }
        fence_async_init();
    }
    __syncthreads();

    const char* srcA = At + (size_t)kb0 * TILEP;
    const char* srcB = Bt + (TRANSB ? ((size_t)jb * 64 + kb0)
                                    : ((size_t)kb0 * 64 + jb)) * TILEP;
    const long dB = TRANSB ? TILEP : (long)64 * TILEP;

    const uint32_t xorv = (uint32_t)(lane & 7) << 4;
    uint32_t aoffs[4];
#pragma unroll
    for (int ks = 0; ks < 4; ks++)
        aoffs[ks] = (uint32_t)(mw + lr) * 128 + (((uint32_t)(ks * 32 + g8 * 2)) ^ xorv);
    uint32_t boffs[4][2];
#pragma unroll
    for (int ks = 0; ks < 4; ks++)
#pragma unroll
        for (int half = 0; half < 2; half++) {
            if (TRANSB == 0)
                boffs[ks][half] = (uint32_t)(ks * 16 + lr) * 128 +
                                  (((uint32_t)((nw + half * 16 + g8) * 2)) ^ xorv);
            else
                boffs[ks][half] = (uint32_t)(nw + half * 16 + lr) * 128 +
                                  (((uint32_t)(ks * 32 + g8 * 2)) ^ xorv);
        }

    float acc[4][4];
#pragma unroll
    for (int nt = 0; nt < 4; nt++)
#pragma unroll
        for (int u = 0; u < 4; u++) acc[nt][u] = 0.0f;

    if (t == 0) {
#pragma unroll
        for (int cn = 0; cn < NST - 1; cn++) {
            uint32_t full = smb + cn * 16;
            mbar_expect_tx(full, TX_BYTES);
            bulk_ld(smb + 128 + cn * STAGE_BYTES,         srcA + (long)cn * TILEP, TILEP, full);
            bulk_ld(smb + 128 + cn * STAGE_BYTES + TILEP, srcB + (long)cn * dB,    TILEP, full);
        }
    }

#pragma unroll
    for (int cb = 0; cb < NCH; cb += NST) {
        const int q    = cb / NST;
        const int cpar = q & 1;
#pragma unroll
        for (int s = 0; s < NST; s++) {
            const int cc = cb + s;
            if (cc >= NCH) break;
            const int cn = cc + NST - 1;
            const int istage = (s + NST - 1) % NST;
            if (cn < NCH && t == 0) {
                if (cn >= NST) {
                    const int ipar = (s == 0) ? ((q - 1) & 1) : cpar;
                    mbar_wait(smb + istage * 16 + 8, ipar);
                }
                const uint32_t full = smb + istage * 16;
                mbar_expect_tx(full, TX_BYTES);
                bulk_ld(smb + 128 + istage * STAGE_BYTES,         srcA + (long)cn * TILEP, TILEP, full);
                bulk_ld(smb + 128 + istage * STAGE_BYTES + TILEP, srcB + (long)cn * dB,    TILEP, full);
            }

            mbar_wait(smb + s * 16, cpar);

            const uint32_t Ah = smb + 128 + s * STAGE_BYTES;
            const uint32_t Al = Ah + 8192;
            const uint32_t Bh = Ah + TILEP;
            const uint32_t Bl = Bh + 8192;

#pragma unroll
            for (int ks = 0; ks < 4; ks++) {
                uint32_t ah[4], al[4];
                ldsm4(ah, Ah + aoffs[ks]);
                ldsm4(al, Al + aoffs[ks]);
#pragma unroll
                for (int half = 0; half < 2; half++) {
                    uint32_t bh[4], bl[4];
                    if (TRANSB == 0) {
                        ldsm4t(bh, Bh + boffs[ks][half]);
                        ldsm4t(bl, Bl + boffs[ks][half]);
                        mma16816(acc[half * 2],     ah, bh[0], bh[1]);
                        mma16816(acc[half * 2],     ah, bl[0], bl[1]);
                        mma16816(acc[half * 2],     al, bh[0], bh[1]);
                        mma16816(acc[half * 2 + 1], ah, bh[2], bh[3]);
                        mma16816(acc[half * 2 + 1], ah, bl[2], bl[3]);
                        mma16816(acc[half * 2 + 1], al, bh[2], bh[3]);
                    } else {
                        ldsm4(bh, Bh + boffs[ks][half]);
                        ldsm4(bl, Bl + boffs[ks][half]);
                        mma16816(acc[half * 2],     ah, bh[0], bh[2]);
                        mma16816(acc[half * 2],     ah, bl[0], bl[2]);
                        mma16816(acc[half * 2],     al, bh[0], bh[2]);
                        mma16816(acc[half * 2 + 1], ah, bh[1], bh[3]);
                        mma16816(acc[half * 2 + 1], ah, bl[1], bl[3]);
                        mma16816(acc[half * 2 + 1], al, bh[1], bh[3]);
                    }
                }
            }
            if (lane == 0) mbar_arrive(smb + s * 16 + 8);
        }
    }

    const int row = mw + (lane >> 2);
#pragma unroll
    for (int nt = 0; nt < 4; nt++) {
        const int col = jg + nw + (nt >> 1) * 16 + (nt & 1) * 8 + (lane & 3) * 2;
        atomicAdd(&C[(size_t)row * NDIM + col],           acc[nt][0]);
        atomicAdd(&C[(size_t)row * NDIM + col + 1],       acc[nt][1]);
        atomicAdd(&C[(size_t)(row + 8) * NDIM + col],     acc[nt][2]);
        atomicAdd(&C[(size_t)(row + 8) * NDIM + col + 1], acc[nt][3]);
    }
}

// ---------------------------------------------------------------------------
// Tensor-core Chebyshev, BNC=16 columns/block, 128 threads, grid 256.
// Columns are independent; narrower blocks double the block count so two
// recurrence chains overlap per SM. Output into tiled/pre-swizzled g_Ztt.
// ---------------------------------------------------------------------------
__global__ __launch_bounds__(128) void cheb_tc(const float* __restrict__ lamS,
                                               const float* __restrict__ gammap) {
    extern __shared__ __align__(16) __nv_bfloat16 cs[];
    __nv_bfloat16* Gh = cs;
    __nv_bfloat16* Gl = cs + 64 * GST;
    __nv_bfloat16* Tbh = cs + 2 * 64 * GST;
    __nv_bfloat16* Tbl = Tbh + 3 * 64 * TST;
    __shared__ float sh_base[BNC];
    __shared__ float sh_r[BNC];

    const int t    = threadIdx.x;
    const int lane = t & 31;
    const int warp = t >> 5;           // 0..3
    const int jg   = blockIdx.x * BNC;
    const int mw   = warp * 16;
    const int lr   = lane & 15;
    const int g8   = (lane >> 4) * 8;

    for (int o = t; o < MDIM * MDIM; o += 128) {
        int r = o >> 6, c = o & 63;
        __nv_bfloat16 h, l;
        bf16split(g_Gt[o], h, l);
        Gh[r * GST + c] = h;
        Gl[r * GST + c] = l;
    }
    for (int o = t; o < MDIM * BNC; o += 128) {
        int r = o >> 4, c = o & 15;
        __nv_bfloat16 h, l;
        bf16split(g_Y[(size_t)r * NDIM + jg + c], h, l);
        Tbh[r * TST + c] = h;
        Tbl[r * TST + c] = l;
    }
    if (t < BNC) {
        float gam = gammap[0];
        float a = gam * lamS[jg + t];
        float base, r;
        if (fabsf(a) < 1e-7f) {
            base = 1.0f; r = 0.0f;
        } else {
            float b  = 2.0f / a - 1.0f;
            float ab = fabsf(b);
            float s  = sqrtf(fmaf(ab, ab, -1.0f));
            float q  = 1.0f / (ab + s);
            float sg = (a > 0.0f) ? 1.0f : -1.0f;
            r    = sg * q;
            base = (2.0f / a) * sg * 2.0f * q / (1.0f - q * q);
        }
        sh_base[t] = base;
        sh_r[t]    = r;
    }
    __syncthreads();

    uint32_t gh[4][4], gl[4][4];
#pragma unroll
    for (int ks = 0; ks < 4; ks++) {
        ldsm4(gh[ks], sptr(Gh + (mw + lr) * GST + ks * 16 + g8));
        ldsm4(gl[ks], sptr(Gl + (mw + lr) * GST + ks * 16 + g8));
    }

    const int row0 = mw + (lane >> 2);
    float basev[2][2], rv[2][2], pv[2][2];
#pragma unroll
    for (int nt = 0; nt < 2; nt++) {
        int c0 = nt * 8 + 2 * (lane & 3);
        basev[nt][0] = sh_base[c0];     basev[nt][1] = sh_base[c0 + 1];
        rv[nt][0]    = sh_r[c0];        rv[nt][1]    = sh_r[c0 + 1];
        pv[nt][0] = 2.0f * basev[nt][0] * rv[nt][0];
        pv[nt][1] = 2.0f * basev[nt][1] * rv[nt][1];
    }

    float acc[2][4], prev[2][4], tp[2][4];
#pragma unroll
    for (int nt = 0; nt < 2; nt++) {
        int c0 = nt * 8 + 2 * (lane & 3);
        float2 y0 = *(const float2*)&g_Y[(size_t)row0 * NDIM + jg + c0];
        float2 y1 = *(const float2*)&g_Y[(size_t)(row0 + 8) * NDIM + jg + c0];
        prev[nt][0] = y0.x; prev[nt][1] = y0.y; prev[nt][2] = y1.x; prev[nt][3] = y1.y;
        acc[nt][0] = basev[nt][0] * y0.x;
        acc[nt][1] = basev[nt][1] * y0.y;
        acc[nt][2] = basev[nt][0] * y1.x;
        acc[nt][3] = basev[nt][1] * y1.y;
        tp[nt][0] = tp[nt][1] = tp[nt][2] = tp[nt][3] = 0.0f;
    }

    for (int k = 1; k < KCHEB; k++) {
        __syncthreads();
        const __nv_bfloat16* Th = Tbh + ((k - 1) % 3) * (64 * TST);
        const __nv_bfloat16* Tl = Tbl + ((k - 1) % 3) * (64 * TST);
        float u[2][4];
#pragma unroll
        for (int nt = 0; nt < 2; nt++)
#pragma unroll
            for (int i = 0; i < 4; i++) u[nt][i] = 0.0f;
#pragma unroll
        for (int ks = 0; ks < 4; ks++) {
            uint32_t th[4], tl[4];
            ldsm4t(th, sptr(Th + (ks * 16 + lr) * TST + g8));
            ldsm4t(tl, sptr(Tl + (ks * 16 + lr) * TST + g8));
            mma16816(u[0], gh[ks], th[0], th[1]);
            mma16816(u[0], gh[ks], tl[0], tl[1]);
            mma16816(u[0], gl[ks], th[0], th[1]);
            mma16816(u[1], gh[ks], th[2], th[3]);
            mma16816(u[1], gh[ks], tl[2], tl[3]);
            mma16816(u[1], gl[ks], th[2], th[3]);
        }
        float tn[2][4];
#pragma unroll
        for (int nt = 0; nt < 2; nt++)
#pragma unroll
            for (int i = 0; i < 4; i++)
                tn[nt][i] = (k == 1) ? u[nt][i] : fmaf(2.0f, u[nt][i], -tp[nt][i]);
#pragma unroll
        for (int nt = 0; nt < 2; nt++) {
            acc[nt][0] = fmaf(pv[nt][0], tn[nt][0], acc[nt][0]);
            acc[nt][1] = fmaf(pv[nt][1], tn[nt][1], acc[nt][1]);
            acc[nt][2] = fmaf(pv[nt][0], tn[nt][2], acc[nt][2]);
            acc[nt][3] = fmaf(pv[nt][1], tn[nt][3], acc[nt][3]);
            pv[nt][0] *= rv[nt][0];
            pv[nt][1] *= rv[nt][1];
        }
        if (k < KCHEB - 1) {
            __nv_bfloat16* Wh = Tbh + (k % 3) * (64 * TST);
            __nv_bfloat16* Wl = Tbl + (k % 3) * (64 * TST);
#pragma unroll
            for (int nt = 0; nt < 2; nt++) {
                int c0 = nt * 8 + 2 * (lane & 3);
                uint32_t hp, lp;
                split2pack(tn[nt][0], tn[nt][1], hp, lp);
                *(uint32_t*)(Wh + row0 * TST + c0) = hp;
                *(uint32_t*)(Wl + row0 * TST + c0) = lp;
                split2pack(tn[nt][2], tn[nt][3], hp, lp);
                *(uint32_t*)(Wh + (row0 + 8) * TST + c0) = hp;
                *(uint32_t*)(Wl + (row0 + 8) * TST + c0) = lp;
            }
        }
#pragma unroll
        for (int nt = 0; nt < 2; nt++)
#pragma unroll
            for (int i = 0; i < 4; i++) {
                tp[nt][i]   = prev[nt][i];
                prev[nt][i] = tn[nt][i];
            }
    }

    // write Z~ into tiled/pre-swizzled g_Ztt
    {
        char* Zt = g_Ztt + (size_t)(jg >> 6) * TILEP;
        const uint32_t jo = jg & 63;
#pragma unroll
        for (int nt = 0; nt < 2; nt++) {
            const uint32_t c0 = nt * 8 + 2 * (lane & 3);
            uint32_t hp, lp;
            split2pack(acc[nt][0], acc[nt][1], hp, lp);
            uint32_t o0 = (uint32_t)row0 * 128 + (((jo + c0) * 2) ^ (((uint32_t)row0 & 7) << 4));
            *(uint32_t*)(Zt + o0)        = hp;
            *(uint32_t*)(Zt + 8192 + o0) = lp;
            split2pack(acc[nt][2], acc[nt][3], hp, lp);
            uint32_t o1 = (uint32_t)(row0 + 8) * 128 + (((jo + c0) * 2) ^ (((uint32_t)row0 & 7) << 4));
            *(uint32_t*)(Zt + o1)        = hp;
            *(uint32_t*)(Zt + 8192 + o1) = lp;
        }
    }
}

#define CHEB_SMEM ((2 * 64 * GST + 6 * 64 * TST) * 2)

// ---------------------------------------------------------------------------
extern "C" void kernel_launch(void* const* d_in, const int* in_sizes, int n_in,
                              void* d_out, int out_size) {
    const float* X    = (const float*)d_in[0];   // (64, 4096)
    const float* F    = (const float*)d_in[1];   // (64, 64)
    const float* Q_S  = (const float*)d_in[2];   // (4096, 4096)
    const float* lamS = (const float*)d_in[3];   // (4096,)
    const float* gam  = (const float*)d_in[4];   // scalar
    float* Z = (float*)d_out;                    // (64, 4096)

    float* Y;
    char *Qt, *Xt, *Ztt;
    cudaGetSymbolAddress((void**)&Y,   g_Y);
    cudaGetSymbolAddress((void**)&Qt,  g_Qt);
    cudaGetSymbolAddress((void**)&Xt,  g_Xt);
    cudaGetSymbolAddress((void**)&Ztt, g_Ztt);

    static bool attr_set = false;
    if (!attr_set) {
        cudaFuncSetAttribute(gemm_bf<0>, cudaFuncAttributeMaxDynamicSharedMemorySize, GEMM_SMEM);
        cudaFuncSetAttribute(gemm_bf<1>, cudaFuncAttributeMaxDynamicSharedMemorySize, GEMM_SMEM);
        cudaFuncSetAttribute(cheb_tc,    cudaFuncAttributeMaxDynamicSharedMemorySize, CHEB_SMEM);
        attr_set = true;
    }

    const int conv_blocks = (NDIM * NDIM / 4 + MDIM * NDIM / 4) / 256;  // 16640
    dim3 ggrid(NDIM / BN, NSPLIT);

    conv_kernel<<<conv_blocks, 256>>>((const float4*)Q_S, (const float4*)X);
    zero_kernel<<<(MDIM * NDIM) / 256, 256>>>(Y, Z);
    prep_kernel<<<1, 256>>>(F);
    gemm_bf<0><<<ggrid, 256, GEMM_SMEM>>>(Xt, Qt, Y);      // Y += X @ Q_S
    cheb_tc<<<NDIM / BNC, 128, CHEB_SMEM>>>(lamS, gam);    // Ztt = f(G) Y (tiled)
    gemm_bf<1><<<ggrid, 256, GEMM_SMEM>>>(Ztt, Qt, Z);     // Z += Z~ @ Q_S^T
}

// round 17
// speedup vs baseline: 1.0961x; 1.0267x over previous
#include <cuda_runtime.h>
#include <cuda_bf16.h>
#include <cstdint>
#include <math.h>

#define MDIM 64
#define NDIM 4096
#define BN   64
#define NST  3
#define KSPL 1024
#define NCH  (KSPL / 64)     // 16 chunks per K-split
#define NSPLIT (NDIM / KSPL) // 4
#define KCHEB 12
#define BNC  16              // cheb columns per block

#define TILEP 16384                    // one 64x64 hi+lo tile pair (8192 + 8192)
#define STAGE_BYTES 32768              // A pair + B pair
#define TX_BYTES 32768
#define GEMM_SMEM (128 + NST * STAGE_BYTES)   // 98432

#define GST 72
#define TST 40

// Scratch (allocation-free rule: __device__ globals)
__device__ float g_Gt[MDIM * MDIM];
__device__ float g_Y [MDIM * NDIM];
// tiled, pre-swizzled bf16 hi/lo tile pairs (16KB each)
__device__ __align__(128) char g_Qt[(size_t)64 * 64 * TILEP];  // Q_S: [rb][cc]
__device__ __align__(128) char g_Xt[64 * TILEP];               // X:   [kc]
__device__ __align__(128) char g_Ztt[64 * TILEP];              // Z~:  [kc]

// ---------------------------------------------------------------------------
// PTX helpers
// ---------------------------------------------------------------------------
__device__ __forceinline__ uint32_t sptr(const void* p) {
    return (uint32_t)__cvta_generic_to_shared(p);
}
__device__ __forceinline__ void ldsm4(uint32_t r[4], uint32_t addr) {
    asm volatile("ldmatrix.sync.aligned.m8n8.x4.shared.b16 {%0,%1,%2,%3}, [%4];"
                 : "=r"(r[0]), "=r"(r[1]), "=r"(r[2]), "=r"(r[3]) : "r"(addr));
}
__device__ __forceinline__ void ldsm4t(uint32_t r[4], uint32_t addr) {
    asm volatile("ldmatrix.sync.aligned.m8n8.x4.trans.shared.b16 {%0,%1,%2,%3}, [%4];"
                 : "=r"(r[0]), "=r"(r[1]), "=r"(r[2]), "=r"(r[3]) : "r"(addr));
}
__device__ __forceinline__ void mma16816(float d[4], const uint32_t a[4],
                                         uint32_t b0, uint32_t b1) {
    asm volatile("mma.sync.aligned.m16n8k16.row.col.f32.bf16.bf16.f32 "
                 "{%0,%1,%2,%3}, {%4,%5,%6,%7}, {%8,%9}, {%0,%1,%2,%3};"
                 : "+f"(d[0]), "+f"(d[1]), "+f"(d[2]), "+f"(d[3])
                 : "r"(a[0]), "r"(a[1]), "r"(a[2]), "r"(a[3]),
                   "r"(b0), "r"(b1));
}
__device__ __forceinline__ void bulk_ld(uint32_t dst, const void* src,
                                        uint32_t bytes, uint32_t mbar) {
    asm volatile("cp.async.bulk.shared::cluster.global.mbarrier::complete_tx::bytes "
                 "[%0], [%1], %2, [%3];"
                 :: "r"(dst), "l"(src), "r"(bytes), "r"(mbar) : "memory");
}
__device__ __forceinline__ void mbar_init(uint32_t a, uint32_t cnt) {
    asm volatile("mbarrier.init.shared.b64 [%0], %1;" :: "r"(a), "r"(cnt) : "memory");
}
__device__ __forceinline__ void mbar_expect_tx(uint32_t a, uint32_t bytes) {
    asm volatile("mbarrier.arrive.expect_tx.shared.b64 _, [%0], %1;"
                 :: "r"(a), "r"(bytes) : "memory");
}
__device__ __forceinline__ void mbar_arrive(uint32_t a) {
    asm volatile("mbarrier.arrive.shared.b64 _, [%0];" :: "r"(a) : "memory");
}
__device__ __forceinline__ void mbar_wait(uint32_t a, uint32_t parity) {
    asm volatile(
        "{\n\t.reg .pred P;\n\t"
        "WAIT_%=:\n\t"
        "mbarrier.try_wait.parity.acquire.cta.shared::cta.b64 P, [%0], %1, 0x989680;\n\t"
        "@P bra.uni DONE_%=;\n\t"
        "bra.uni WAIT_%=;\n\t"
        "DONE_%=:\n\t}"
        :: "r"(a), "r"(parity) : "memory");
}
__device__ __forceinline__ void fence_async_init() {
    asm volatile("fence.proxy.async.shared::cta;" ::: "memory");
}

__device__ __forceinline__ void bf16split(float x, __nv_bfloat16& h, __nv_bfloat16& l) {
    h = __float2bfloat16(x);
    l = __float2bfloat16(x - __bfloat162float(h));
}
__device__ __forceinline__ void split2pack(float a, float b, uint32_t& hp, uint32_t& lp) {
    __nv_bfloat16 ha, la, hb, lb;
    bf16split(a, ha, la);
    bf16split(b, hb, lb);
    __nv_bfloat162 h; h.x = ha; h.y = hb;
    __nv_bfloat162 l; l.x = la; l.y = lb;
    hp = *(uint32_t*)&h;
    lp = *(uint32_t*)&l;
}

// ---------------------------------------------------------------------------
// Convert Q_S and X into tiled, pre-swizzled bf16 hi/lo tile pairs.
// Each thread: 8 consecutive floats of one row -> ONE 16B store to hi and
// ONE 16B store to lo (swizzle is 16B-granular, stores stay aligned).
// ---------------------------------------------------------------------------
__global__ __launch_bounds__(256) void conv_kernel(const float4* __restrict__ Q,
                                                   const float4* __restrict__ X) {
    const size_t QN8 = (size_t)NDIM * NDIM / 8;
    size_t gid = (size_t)blockIdx.x * 256 + threadIdx.x;
    float4 v0, v1;
    char* base;
    uint32_t r, c;
    if (gid < QN8) {
        v0 = Q[2 * gid];
        v1 = Q[2 * gid + 1];
        r = (uint32_t)(gid >> 9);
        c = ((uint32_t)gid & 511) * 8;
        base = g_Qt + ((size_t)((r >> 6) * 64 + (c >> 6))) * TILEP;
    } else {
        size_t x = gid - QN8;
        v0 = X[2 * x];
        v1 = X[2 * x + 1];
        r = (uint32_t)(x >> 9);
        c = ((uint32_t)x & 511) * 8;
        base = g_Xt + (size_t)(c >> 6) * TILEP;
    }
    const uint32_t i = r & 63, j = c & 63;
    const uint32_t sw = (i * 128 + j * 2) ^ ((i & 7) << 4);
    uint32_t h0, l0, h1, l1, h2, l2, h3, l3;
    split2pack(v0.x, v0.y, h0, l0);
    split2pack(v0.z, v0.w, h1, l1);
    split2pack(v1.x, v1.y, h2, l2);
    split2pack(v1.z, v1.w, h3, l3);
    *(uint4*)(base + sw)        = make_uint4(h0, h1, h2, h3);
    *(uint4*)(base + 8192 + sw) = make_uint4(l0, l1, l2, l3);
}

// ---------------------------------------------------------------------------
// Zero-init Y and Z (outputs accumulated via atomicAdd each replay)
// ---------------------------------------------------------------------------
__global__ __launch_bounds__(256) void zero_kernel(float* __restrict__ a,
                                                   float* __restrict__ b) {
    int i = blockIdx.x * 256 + threadIdx.x;
    a[i] = 0.0f;
    b[i] = 0.0f;
}

// ---------------------------------------------------------------------------
// G~ = 2 * (F^T F) / (||F^T F||_F + 1e-12) - I
// ---------------------------------------------------------------------------
__global__ __launch_bounds__(256) void prep_kernel(const float* __restrict__ F) {
    __shared__ float Fs[MDIM][MDIM + 1];
    __shared__ float FFs[MDIM][MDIM + 4];
    __shared__ float red[8];
    __shared__ float s_inv;

    int t = threadIdx.x;
    for (int o = t; o < MDIM * MDIM; o += 256)
        Fs[o >> 6][o & 63] = F[o];
    __syncthreads();

    int i  = t >> 2;
    int j0 = (t & 3) * 16;
    float acc[16];
#pragma unroll
    for (int u = 0; u < 16; u++) acc[u] = 0.0f;
    for (int k = 0; k < MDIM; k++) {
        float a = Fs[k][i];
#pragma unroll
        for (int u = 0; u < 16; u++) acc[u] = fmaf(a, Fs[k][j0 + u], acc[u]);
    }
    float ss = 0.0f;
#pragma unroll
    for (int u = 0; u < 16; u++) {
        FFs[i][j0 + u] = acc[u];
        ss = fmaf(acc[u], acc[u], ss);
    }
#pragma unroll
    for (int off = 16; off > 0; off >>= 1)
        ss += __shfl_xor_sync(0xffffffffu, ss, off);
    if ((t & 31) == 0) red[t >> 5] = ss;
    __syncthreads();
    if (t == 0) {
        float tot = 0.0f;
        for (int w = 0; w < 8; w++) tot += red[w];
        s_inv = 2.0f / (sqrtf(tot) + 1e-12f);
    }
    __syncthreads();
    float inv = s_inv;
#pragma unroll
    for (int u = 0; u < 16; u++) {
        int j = j0 + u;
        g_Gt[i * MDIM + j] = FFs[i][j] * inv - (i == j ? 1.0f : 0.0f);
    }
}

// ---------------------------------------------------------------------------
// TMA-staged bf16 tensor GEMM on pre-swizzled tiles (R12 core, verbatim).
// NST=3 ring, 2 TMA bulks/chunk by thread 0, empty barriers (count 8).
// TRANSB=0: B tile = Qt[kc][jb];  TRANSB=1: B tile = Qt[jb][kc].
// ---------------------------------------------------------------------------
template <int TRANSB>
__global__ __launch_bounds__(256) void gemm_bf(const char* __restrict__ At,
                                               const char* __restrict__ Bt,
                                               float* __restrict__ C) {
    extern __shared__ __align__(128) char sm[];
    const uint32_t smb = sptr(sm);

    const int t    = threadIdx.x;
    const int lane = t & 31;
    const int warp = t >> 5;
    const int jb   = blockIdx.x;
    const int jg   = jb * BN;
    const int kb0  = blockIdx.y * (KSPL / 64);
    const int mw   = (warp & 3) * 16;
    const int nw   = (warp >> 2) * 32;
    const int lr   = lane & 15;
    const int g8   = (lane >> 4) * 8;

    if (t == 0) {
#pragma unroll
        for (int s = 0; s < NST; s++) {
            mbar_init(smb + s * 16, 1);     // full
            mbar_init(smb + s * 16 + 8, 8); // empty (one arrive per warp)
        }
        fence_async_init();
    }
    __syncthreads();

    const char* srcA = At + (size_t)kb0 * TILEP;
    const char* srcB = Bt + (TRANSB ? ((size_t)jb * 64 + kb0)
                                    : ((size_t)kb0 * 64 + jb)) * TILEP;
    const long dB = TRANSB ? TILEP : (long)64 * TILEP;

    const uint32_t xorv = (uint32_t)(lane & 7) << 4;
    uint32_t aoffs[4];
#pragma unroll
    for (int ks = 0; ks < 4; ks++)
        aoffs[ks] = (uint32_t)(mw + lr) * 128 + (((uint32_t)(ks * 32 + g8 * 2)) ^ xorv);
    uint32_t boffs[4][2];
#pragma unroll
    for (int ks = 0; ks < 4; ks++)
#pragma unroll
        for (int half = 0; half < 2; half++) {
            if (TRANSB == 0)
                boffs[ks][half] = (uint32_t)(ks * 16 + lr) * 128 +
                                  (((uint32_t)((nw + half * 16 + g8) * 2)) ^ xorv);
            else
                boffs[ks][half] = (uint32_t)(nw + half * 16 + lr) * 128 +
                                  (((uint32_t)(ks * 32 + g8 * 2)) ^ xorv);
        }

    float acc[4][4];
#pragma unroll
    for (int nt = 0; nt < 4; nt++)
#pragma unroll
        for (int u = 0; u < 4; u++) acc[nt][u] = 0.0f;

    if (t == 0) {
#pragma unroll
        for (int cn = 0; cn < NST - 1; cn++) {
            uint32_t full = smb + cn * 16;
            mbar_expect_tx(full, TX_BYTES);
            bulk_ld(smb + 128 + cn * STAGE_BYTES,         srcA + (long)cn * TILEP, TILEP, full);
            bulk_ld(smb + 128 + cn * STAGE_BYTES + TILEP, srcB + (long)cn * dB,    TILEP, full);
        }
    }

#pragma unroll
    for (int cb = 0; cb < NCH; cb += NST) {
        const int q    = cb / NST;
        const int cpar = q & 1;
#pragma unroll
        for (int s = 0; s < NST; s++) {
            const int cc = cb + s;
            if (cc >= NCH) break;
            const int cn = cc + NST - 1;
            const int istage = (s + NST - 1) % NST;
            if (cn < NCH && t == 0) {
                if (cn >= NST) {
                    const int ipar = (s == 0) ? ((q - 1) & 1) : cpar;
                    mbar_wait(smb + istage * 16 + 8, ipar);
                }
                const uint32_t full = smb + istage * 16;
                mbar_expect_tx(full, TX_BYTES);
                bulk_ld(smb + 128 + istage * STAGE_BYTES,         srcA + (long)cn * TILEP, TILEP, full);
                bulk_ld(smb + 128 + istage * STAGE_BYTES + TILEP, srcB + (long)cn * dB,    TILEP, full);
            }

            mbar_wait(smb + s * 16, cpar);

            const uint32_t Ah = smb + 128 + s * STAGE_BYTES;
            const uint32_t Al = Ah + 8192;
            const uint32_t Bh = Ah + TILEP;
            const uint32_t Bl = Bh + 8192;

#pragma unroll
            for (int ks = 0; ks < 4; ks++) {
                uint32_t ah[4], al[4];
                ldsm4(ah, Ah + aoffs[ks]);
                ldsm4(al, Al + aoffs[ks]);
#pragma unroll
                for (int half = 0; half < 2; half++) {
                    uint32_t bh[4], bl[4];
                    if (TRANSB == 0) {
                        ldsm4t(bh, Bh + boffs[ks][half]);
                        ldsm4t(bl, Bl + boffs[ks][half]);
                        mma16816(acc[half * 2],     ah, bh[0], bh[1]);
                        mma16816(acc[half * 2],     ah, bl[0], bl[1]);
                        mma16816(acc[half * 2],     al, bh[0], bh[1]);
                        mma16816(acc[half * 2 + 1], ah, bh[2], bh[3]);
                        mma16816(acc[half * 2 + 1], ah, bl[2], bl[3]);
                        mma16816(acc[half * 2 + 1], al, bh[2], bh[3]);
                    } else {
                        ldsm4(bh, Bh + boffs[ks][half]);
                        ldsm4(bl, Bl + boffs[ks][half]);
                        mma16816(acc[half * 2],     ah, bh[0], bh[2]);
                        mma16816(acc[half * 2],     ah, bl[0], bl[2]);
                        mma16816(acc[half * 2],     al, bh[0], bh[2]);
                        mma16816(acc[half * 2 + 1], ah, bh[1], bh[3]);
                        mma16816(acc[half * 2 + 1], ah, bl[1], bl[3]);
                        mma16816(acc[half * 2 + 1], al, bh[1], bh[3]);
                    }
                }
            }
            if (lane == 0) mbar_arrive(smb + s * 16 + 8);
        }
    }

    const int row = mw + (lane >> 2);
#pragma unroll
    for (int nt = 0; nt < 4; nt++) {
        const int col = jg + nw + (nt >> 1) * 16 + (nt & 1) * 8 + (lane & 3) * 2;
        atomicAdd(&C[(size_t)row * NDIM + col],           acc[nt][0]);
        atomicAdd(&C[(size_t)row * NDIM + col + 1],       acc[nt][1]);
        atomicAdd(&C[(size_t)(row + 8) * NDIM + col],     acc[nt][2]);
        atomicAdd(&C[(size_t)(row + 8) * NDIM + col + 1], acc[nt][3]);
    }
}

// ---------------------------------------------------------------------------
// Tensor-core Chebyshev, BNC=16 columns/block, 128 threads, grid 256.
// ---------------------------------------------------------------------------
__global__ __launch_bounds__(128) void cheb_tc(const float* __restrict__ lamS,
                                               const float* __restrict__ gammap) {
    extern __shared__ __align__(16) __nv_bfloat16 cs[];
    __nv_bfloat16* Gh = cs;
    __nv_bfloat16* Gl = cs + 64 * GST;
    __nv_bfloat16* Tbh = cs + 2 * 64 * GST;
    __nv_bfloat16* Tbl = Tbh + 3 * 64 * TST;
    __shared__ float sh_base[BNC];
    __shared__ float sh_r[BNC];

    const int t    = threadIdx.x;
    const int lane = t & 31;
    const int warp = t >> 5;           // 0..3
    const int jg   = blockIdx.x * BNC;
    const int mw   = warp * 16;
    const int lr   = lane & 15;
    const int g8   = (lane >> 4) * 8;

    for (int o = t; o < MDIM * MDIM; o += 128) {
        int r = o >> 6, c = o & 63;
        __nv_bfloat16 h, l;
        bf16split(g_Gt[o], h, l);
        Gh[r * GST + c] = h;
        Gl[r * GST + c] = l;
    }
    for (int o = t; o < MDIM * BNC; o += 128) {
        int r = o >> 4, c = o & 15;
        __nv_bfloat16 h, l;
        bf16split(g_Y[(size_t)r * NDIM + jg + c], h, l);
        Tbh[r * TST + c] = h;
        Tbl[r * TST + c] = l;
    }
    if (t < BNC) {
        float gam = gammap[0];
        float a = gam * lamS[jg + t];
        float base, r;
        if (fabsf(a) < 1e-7f) {
            base = 1.0f; r = 0.0f;
        } else {
            float b  = 2.0f / a - 1.0f;
            float ab = fabsf(b);
            float s  = sqrtf(fmaf(ab, ab, -1.0f));
            float q  = 1.0f / (ab + s);
            float sg = (a > 0.0f) ? 1.0f : -1.0f;
            r    = sg * q;
            base = (2.0f / a) * sg * 2.0f * q / (1.0f - q * q);
        }
        sh_base[t] = base;
        sh_r[t]    = r;
    }
    __syncthreads();

    uint32_t gh[4][4], gl[4][4];
#pragma unroll
    for (int ks = 0; ks < 4; ks++) {
        ldsm4(gh[ks], sptr(Gh + (mw + lr) * GST + ks * 16 + g8));
        ldsm4(gl[ks], sptr(Gl + (mw + lr) * GST + ks * 16 + g8));
    }

    const int row0 = mw + (lane >> 2);
    float basev[2][2], rv[2][2], pv[2][2];
#pragma unroll
    for (int nt = 0; nt < 2; nt++) {
        int c0 = nt * 8 + 2 * (lane & 3);
        basev[nt][0] = sh_base[c0];     basev[nt][1] = sh_base[c0 + 1];
        rv[nt][0]    = sh_r[c0];        rv[nt][1]    = sh_r[c0 + 1];
        pv[nt][0] = 2.0f * basev[nt][0] * rv[nt][0];
        pv[nt][1] = 2.0f * basev[nt][1] * rv[nt][1];
    }

    float acc[2][4], prev[2][4], tp[2][4];
#pragma unroll
    for (int nt = 0; nt < 2; nt++) {
        int c0 = nt * 8 + 2 * (lane & 3);
        float2 y0 = *(const float2*)&g_Y[(size_t)row0 * NDIM + jg + c0];
        float2 y1 = *(const float2*)&g_Y[(size_t)(row0 + 8) * NDIM + jg + c0];
        prev[nt][0] = y0.x; prev[nt][1] = y0.y; prev[nt][2] = y1.x; prev[nt][3] = y1.y;
        acc[nt][0] = basev[nt][0] * y0.x;
        acc[nt][1] = basev[nt][1] * y0.y;
        acc[nt][2] = basev[nt][0] * y1.x;
        acc[nt][3] = basev[nt][1] * y1.y;
        tp[nt][0] = tp[nt][1] = tp[nt][2] = tp[nt][3] = 0.0f;
    }

    for (int k = 1; k < KCHEB; k++) {
        __syncthreads();
        const __nv_bfloat16* Th = Tbh + ((k - 1) % 3) * (64 * TST);
        const __nv_bfloat16* Tl = Tbl + ((k - 1) % 3) * (64 * TST);
        float u[2][4];
#pragma unroll
        for (int nt = 0; nt < 2; nt++)
#pragma unroll
            for (int i = 0; i < 4; i++) u[nt][i] = 0.0f;
#pragma unroll
        for (int ks = 0; ks < 4; ks++) {
            uint32_t th[4], tl[4];
            ldsm4t(th, sptr(Th + (ks * 16 + lr) * TST + g8));
            ldsm4t(tl, sptr(Tl + (ks * 16 + lr) * TST + g8));
            mma16816(u[0], gh[ks], th[0], th[1]);
            mma16816(u[0], gh[ks], tl[0], tl[1]);
            mma16816(u[0], gl[ks], th[0], th[1]);
            mma16816(u[1], gh[ks], th[2], th[3]);
            mma16816(u[1], gh[ks], tl[2], tl[3]);
            mma16816(u[1], gl[ks], th[2], th[3]);
        }
        float tn[2][4];
#pragma unroll
        for (int nt = 0; nt < 2; nt++)
#pragma unroll
            for (int i = 0; i < 4; i++)
                tn[nt][i] = (k == 1) ? u[nt][i] : fmaf(2.0f, u[nt][i], -tp[nt][i]);
#pragma unroll
        for (int nt = 0; nt < 2; nt++) {
            acc[nt][0] = fmaf(pv[nt][0], tn[nt][0], acc[nt][0]);
            acc[nt][1] = fmaf(pv[nt][1], tn[nt][1], acc[nt][1]);
            acc[nt][2] = fmaf(pv[nt][0], tn[nt][2], acc[nt][2]);
            acc[nt][3] = fmaf(pv[nt][1], tn[nt][3], acc[nt][3]);
            pv[nt][0] *= rv[nt][0];
            pv[nt][1] *= rv[nt][1];
        }
        if (k < KCHEB - 1) {
            __nv_bfloat16* Wh = Tbh + (k % 3) * (64 * TST);
            __nv_bfloat16* Wl = Tbl + (k % 3) * (64 * TST);
#pragma unroll
            for (int nt = 0; nt < 2; nt++) {
                int c0 = nt * 8 + 2 * (lane & 3);
                uint32_t hp, lp;
                split2pack(tn[nt][0], tn[nt][1], hp, lp);
                *(uint32_t*)(Wh + row0 * TST + c0) = hp;
                *(uint32_t*)(Wl + row0 * TST + c0) = lp;
                split2pack(tn[nt][2], tn[nt][3], hp, lp);
                *(uint32_t*)(Wh + (row0 + 8) * TST + c0) = hp;
                *(uint32_t*)(Wl + (row0 + 8) * TST + c0) = lp;
            }
        }
#pragma unroll
        for (int nt = 0; nt < 2; nt++)
#pragma unroll
            for (int i = 0; i < 4; i++) {
                tp[nt][i]   = prev[nt][i];
                prev[nt][i] = tn[nt][i];
            }
    }

    // write Z~ into tiled/pre-swizzled g_Ztt
    {
        char* Zt = g_Ztt + (size_t)(jg >> 6) * TILEP;
        const uint32_t jo = jg & 63;
#pragma unroll
        for (int nt = 0; nt < 2; nt++) {
            const uint32_t c0 = nt * 8 + 2 * (lane & 3);
            uint32_t hp, lp;
            split2pack(acc[nt][0], acc[nt][1], hp, lp);
            uint32_t o0 = (uint32_t)row0 * 128 + (((jo + c0) * 2) ^ (((uint32_t)row0 & 7) << 4));
            *(uint32_t*)(Zt + o0)        = hp;
            *(uint32_t*)(Zt + 8192 + o0) = lp;
            split2pack(acc[nt][2], acc[nt][3], hp, lp);
            uint32_t o1 = (uint32_t)(row0 + 8) * 128 + (((jo + c0) * 2) ^ (((uint32_t)row0 & 7) << 4));
            *(uint32_t*)(Zt + o1)        = hp;
            *(uint32_t*)(Zt + 8192 + o1) = lp;
        }
    }
}

#define CHEB_SMEM ((2 * 64 * GST + 6 * 64 * TST) * 2)

// ---------------------------------------------------------------------------
extern "C" void kernel_launch(void* const* d_in, const int* in_sizes, int n_in,
                              void* d_out, int out_size) {
    const float* X    = (const float*)d_in[0];   // (64, 4096)
    const float* F    = (const float*)d_in[1];   // (64, 64)
    const float* Q_S  = (const float*)d_in[2];   // (4096, 4096)
    const float* lamS = (const float*)d_in[3];   // (4096,)
    const float* gam  = (const float*)d_in[4];   // scalar
    float* Z = (float*)d_out;                    // (64, 4096)

    float* Y;
    char *Qt, *Xt, *Ztt;
    cudaGetSymbolAddress((void**)&Y,   g_Y);
    cudaGetSymbolAddress((void**)&Qt,  g_Qt);
    cudaGetSymbolAddress((void**)&Xt,  g_Xt);
    cudaGetSymbolAddress((void**)&Ztt, g_Ztt);

    static bool attr_set = false;
    if (!attr_set) {
        cudaFuncSetAttribute(gemm_bf<0>, cudaFuncAttributeMaxDynamicSharedMemorySize, GEMM_SMEM);
        cudaFuncSetAttribute(gemm_bf<1>, cudaFuncAttributeMaxDynamicSharedMemorySize, GEMM_SMEM);
        cudaFuncSetAttribute(cheb_tc,    cudaFuncAttributeMaxDynamicSharedMemorySize, CHEB_SMEM);
        attr_set = true;
    }

    const int conv_blocks = (NDIM * NDIM / 8 + MDIM * NDIM / 8) / 256;  // 8320
    dim3 ggrid(NDIM / BN, NSPLIT);

    conv_kernel<<<conv_blocks, 256>>>((const float4*)Q_S, (const float4*)X);
    zero_kernel<<<(MDIM * NDIM) / 256, 256>>>(Y, Z);
    prep_kernel<<<1, 256>>>(F);
    gemm_bf<0><<<ggrid, 256, GEMM_SMEM>>>(Xt, Qt, Y);      // Y += X @ Q_S
    cheb_tc<<<NDIM / BNC, 128, CHEB_SMEM>>>(lamS, gam);    // Ztt = f(G) Y (tiled)
    gemm_bf<1><<<ggrid, 256, GEMM_SMEM>>>(Ztt, Qt, Z);     // Z += Z~ @ Q_S^T
}